// round 1
// baseline (speedup 1.0000x reference)
#include <cuda_runtime.h>
#include <math.h>

#define BB 8
#define NN 2048
#define NP (BB*NN)      // 16384 points
#define DD 64
#define KK 8
#define LL 3
#define H1 256
#define H2 128

// ---- scratch (device globals; no allocation allowed) ----
__device__ float g_feat[NP*DD];       // 4 MB
__device__ float g_fw[NP*LL];         // 192 KB
__device__ int   g_idx[NP*KK];        // 512 KB
__device__ float g_fcfn[NP*2*DD];     // 8 MB  (per point: [fc(64) | fn(64)])
__device__ float g_agg[NP*DD];        // 4 MB

__device__ __forceinline__ float leaky_f(float v) { return v > 0.f ? v : 0.2f*v; }

// ============================================================
// Kernel 1: feat = leaky((x@W1+b1)*g1+be1); fw = sigmoid(relu(x@Ws1+bs1)@Ws2+bs2)
// thread per point
// ============================================================
__global__ __launch_bounds__(256)
void k_feat(const float* __restrict__ x,
            const float* __restrict__ W1, const float* __restrict__ b1,
            const float* __restrict__ g1, const float* __restrict__ be1,
            const float* __restrict__ Ws1, const float* __restrict__ bs1,
            const float* __restrict__ Ws2, const float* __restrict__ bs2)
{
    int p = blockIdx.x * blockDim.x + threadIdx.x;
    if (p >= NP) return;
    float x0 = x[p*3+0], x1 = x[p*3+1], x2 = x[p*3+2];

    #pragma unroll 8
    for (int d = 0; d < DD; ++d) {
        float v = b1[d] + x0*W1[d] + x1*W1[64+d] + x2*W1[128+d];
        v = v * g1[d] + be1[d];
        g_feat[p*DD + d] = leaky_f(v);
    }

    float h[64];
    #pragma unroll 8
    for (int j = 0; j < 64; ++j) {
        float v = bs1[j] + x0*Ws1[j] + x1*Ws1[64+j] + x2*Ws1[128+j];
        h[j] = v > 0.f ? v : 0.f;
    }
    float a0 = bs2[0], a1 = bs2[1], a2 = bs2[2];
    #pragma unroll 8
    for (int j = 0; j < 64; ++j) {
        float hv = h[j];
        a0 = fmaf(hv, Ws2[j*3+0], a0);
        a1 = fmaf(hv, Ws2[j*3+1], a1);
        a2 = fmaf(hv, Ws2[j*3+2], a2);
    }
    g_fw[p*3+0] = 1.f/(1.f + expf(-a0));
    g_fw[p*3+1] = 1.f/(1.f + expf(-a1));
    g_fw[p*3+2] = 1.f/(1.f + expf(-a2));
}

// ============================================================
// Kernel 2: KNN (8 nearest incl. self). d2 = x2[n]+x2[m]-2*dot (ref formula).
// 128 threads/block = 128 points; batch x cached in smem as float4(x,y,z,|x|^2)
// ============================================================
__global__ __launch_bounds__(128)
void k_knn(const float* __restrict__ x)
{
    __shared__ float4 xs[NN];
    int tid = threadIdx.x;
    int b   = blockIdx.x >> 4;              // 16 blocks per batch
    int n   = ((blockIdx.x & 15) << 7) + tid;
    const float* xb = x + (size_t)b * NN * 3;

    for (int i = tid; i < NN; i += 128) {
        float a0 = xb[i*3+0], a1 = xb[i*3+1], a2 = xb[i*3+2];
        xs[i] = make_float4(a0, a1, a2, a0*a0 + a1*a1 + a2*a2);
    }
    __syncthreads();

    float4 me = xs[n];
    float bd[KK]; int bi[KK];
    #pragma unroll
    for (int k = 0; k < KK; ++k) { bd[k] = 3.4e38f; bi[k] = 0; }

    #pragma unroll 4
    for (int m = 0; m < NN; ++m) {
        float4 q = xs[m];
        float d2 = me.w + q.w - 2.f*(me.x*q.x + me.y*q.y + me.z*q.z);
        if (d2 < bd[KK-1]) {
            float v = d2; int vi = m;
            #pragma unroll
            for (int k = 0; k < KK; ++k) {
                if (v < bd[k]) {
                    float td = bd[k]; int ti = bi[k];
                    bd[k] = v; bi[k] = vi; v = td; vi = ti;
                }
            }
        }
    }
    int gp = b*NN + n;
    #pragma unroll
    for (int k = 0; k < KK; ++k) g_idx[gp*KK + k] = bi[k];
}

// ============================================================
// Kernel 3: [fc|fn] = feat @ [W2[:64] | W2[64:]]  ([16384,64] x [64,128])
// 128 threads/block, 32 points/block. feat tile transposed in smem.
// ============================================================
__global__ __launch_bounds__(128)
void k_fcfn(const float* __restrict__ W2)
{
    __shared__ __align__(16) float fs[64*36];   // feat^T tile, pad 36 (16B-aligned float4 rows)
    __shared__ float ws[64*128];                // combined weights
    int tid = threadIdx.x;
    int pb  = blockIdx.x * 32;

    for (int i = tid; i < 32*64; i += 128) {
        int p = i >> 6, c = i & 63;
        fs[c*36 + p] = g_feat[(size_t)(pb+p)*DD + c];
    }
    for (int i = tid; i < 64*128; i += 128) {
        int c = i >> 7, j = i & 127;
        ws[i] = (j < 64) ? W2[c*64 + j] : W2[(64+c)*64 + (j-64)];
    }
    __syncthreads();

    int j = tid;
    float acc[32];
    #pragma unroll
    for (int p = 0; p < 32; ++p) acc[p] = 0.f;

    #pragma unroll 4
    for (int c = 0; c < 64; ++c) {
        float w = ws[c*128 + j];
        const float4* f4 = (const float4*)(fs + c*36);
        #pragma unroll
        for (int q = 0; q < 8; ++q) {
            float4 f = f4[q];
            acc[4*q+0] = fmaf(f.x, w, acc[4*q+0]);
            acc[4*q+1] = fmaf(f.y, w, acc[4*q+1]);
            acc[4*q+2] = fmaf(f.z, w, acc[4*q+2]);
            acc[4*q+3] = fmaf(f.w, w, acc[4*q+3]);
        }
    }
    #pragma unroll
    for (int p = 0; p < 32; ++p)
        g_fcfn[(size_t)(pb+p)*128 + j] = acc[p];
}

// ============================================================
// Kernel 4: conv = leaky((fc + fn[neighbor] + b2)*g2 + be2); agg = max over k
// thread per (point, d)
// ============================================================
__global__ __launch_bounds__(256)
void k_edge(const float* __restrict__ b2,
            const float* __restrict__ g2,
            const float* __restrict__ be2)
{
    int g = blockIdx.x * 256 + threadIdx.x;   // 16384*64 threads
    int p = g >> 6, d = g & 63;
    int b = p >> 11;
    float fc  = g_fcfn[(size_t)p*128 + d];
    float b2d = b2[d], g2d = g2[d], be2d = be2[d];
    float base = fc + b2d;
    const int* ip = g_idx + (size_t)p*KK;
    size_t rowb = (size_t)(b << 11) * 128;

    float mx = -3.4e38f;
    #pragma unroll
    for (int k = 0; k < KK; ++k) {
        int m = ip[k];
        float fn = g_fcfn[rowb + (size_t)m*128 + 64 + d];
        float v = (base + fn) * g2d + be2d;
        mx = fmaxf(mx, leaky_f(v));
    }
    g_agg[(size_t)p*DD + d] = mx;
}

// ============================================================
// Kernel 5: fusion MLP, fully fused per 16-point tile.
// multi[l*64+d] = agg[d]*fw[l]; h1=leaky(BN(multi@Wf1+bf1)); h2=...; out=x+0.1*delta
// 256 threads/block, 16 points/block, all intermediates in smem (pad 20).
// ============================================================
#define TP 16
#define PP 20
__global__ __launch_bounds__(256)
void k_fusion(const float* __restrict__ x,
              const float* __restrict__ Wf1, const float* __restrict__ bf1,
              const float* __restrict__ gf1, const float* __restrict__ bef1,
              const float* __restrict__ Wf2, const float* __restrict__ bf2,
              const float* __restrict__ gf2, const float* __restrict__ bef2,
              const float* __restrict__ Wf3, const float* __restrict__ bf3,
              float* __restrict__ out)
{
    __shared__ __align__(16) float multi_s[192*PP];  // 15360 B
    __shared__ __align__(16) float h1_s[256*PP];     // 20480 B
    __shared__ __align__(16) float h2_s[128*PP];     // 10240 B
    int tid = threadIdx.x;
    int pb  = blockIdx.x * TP;

    // Phase A: build multi (coalesced agg reads)
    for (int i = tid; i < TP*192; i += 256) {
        int p = i / 192, kk = i - p*192;
        int l = kk >> 6, d = kk & 63;
        multi_s[kk*PP + p] = g_agg[(size_t)(pb+p)*DD + d] * g_fw[(size_t)(pb+p)*3 + l];
    }
    __syncthreads();

    // Phase B: h1 (256 cols, thread per col)
    {
        int j = tid;
        float acc[TP];
        #pragma unroll
        for (int p = 0; p < TP; ++p) acc[p] = 0.f;
        #pragma unroll 2
        for (int kk = 0; kk < 192; ++kk) {
            float w = Wf1[kk*256 + j];
            const float4* m4 = (const float4*)(multi_s + kk*PP);
            #pragma unroll
            for (int q = 0; q < 4; ++q) {
                float4 f = m4[q];
                acc[4*q+0] = fmaf(f.x, w, acc[4*q+0]);
                acc[4*q+1] = fmaf(f.y, w, acc[4*q+1]);
                acc[4*q+2] = fmaf(f.z, w, acc[4*q+2]);
                acc[4*q+3] = fmaf(f.w, w, acc[4*q+3]);
            }
        }
        float bj = bf1[j], gj = gf1[j], bej = bef1[j];
        #pragma unroll
        for (int p = 0; p < TP; ++p) {
            float v = (acc[p] + bj) * gj + bej;
            h1_s[j*PP + p] = leaky_f(v);
        }
    }
    __syncthreads();

    // Phase C: h2 (128 cols, 2 threads per col: p halves)
    {
        int j  = tid & 127;
        int ph = (tid >> 7) * 8;
        float acc[8];
        #pragma unroll
        for (int q = 0; q < 8; ++q) acc[q] = 0.f;
        #pragma unroll 2
        for (int kk = 0; kk < 256; ++kk) {
            float w = Wf2[kk*128 + j];
            const float* hb = h1_s + kk*PP + ph;
            float4 u0 = *(const float4*)(hb);
            float4 u1 = *(const float4*)(hb + 4);
            acc[0] = fmaf(u0.x, w, acc[0]);
            acc[1] = fmaf(u0.y, w, acc[1]);
            acc[2] = fmaf(u0.z, w, acc[2]);
            acc[3] = fmaf(u0.w, w, acc[3]);
            acc[4] = fmaf(u1.x, w, acc[4]);
            acc[5] = fmaf(u1.y, w, acc[5]);
            acc[6] = fmaf(u1.z, w, acc[6]);
            acc[7] = fmaf(u1.w, w, acc[7]);
        }
        float bj = bf2[j], gj = gf2[j], bej = bef2[j];
        #pragma unroll
        for (int q = 0; q < 8; ++q) {
            float v = (acc[q] + bj) * gj + bej;
            h2_s[j*PP + ph + q] = leaky_f(v);
        }
    }
    __syncthreads();

    // Phase D: delta + residual output (48 outputs)
    if (tid < TP*3) {
        int p = tid / 3, c = tid - p*3;
        float acc = 0.f;
        #pragma unroll 4
        for (int kk = 0; kk < 128; ++kk)
            acc = fmaf(h2_s[kk*PP + p], Wf3[kk*3 + c], acc);
        size_t o = (size_t)(pb+p)*3 + c;
        out[o] = x[o] + 0.1f * (acc + bf3[c]);
    }
}

// ============================================================
extern "C" void kernel_launch(void* const* d_in, const int* in_sizes, int n_in,
                              void* d_out, int out_size)
{
    const float* x   = (const float*)d_in[0];
    const float* W1  = (const float*)d_in[1];
    const float* b1  = (const float*)d_in[2];
    const float* g1  = (const float*)d_in[3];
    const float* be1 = (const float*)d_in[4];
    const float* W2  = (const float*)d_in[5];
    const float* b2  = (const float*)d_in[6];
    const float* g2  = (const float*)d_in[7];
    const float* be2 = (const float*)d_in[8];
    const float* Ws1 = (const float*)d_in[9];
    const float* bs1 = (const float*)d_in[10];
    const float* Ws2 = (const float*)d_in[11];
    const float* bs2 = (const float*)d_in[12];
    const float* Wf1 = (const float*)d_in[13];
    const float* bf1 = (const float*)d_in[14];
    const float* gf1 = (const float*)d_in[15];
    const float* bef1= (const float*)d_in[16];
    const float* Wf2 = (const float*)d_in[17];
    const float* bf2 = (const float*)d_in[18];
    const float* gf2 = (const float*)d_in[19];
    const float* bef2= (const float*)d_in[20];
    const float* Wf3 = (const float*)d_in[21];
    const float* bf3 = (const float*)d_in[22];
    float* out = (float*)d_out;

    k_feat<<<NP/256, 256>>>(x, W1, b1, g1, be1, Ws1, bs1, Ws2, bs2);
    k_knn<<<NP/128, 128>>>(x);
    k_fcfn<<<NP/32, 128>>>(W2);
    k_edge<<<(NP*DD)/256, 256>>>(b2, g2, be2);
    k_fusion<<<NP/TP, 256>>>(x, Wf1, bf1, gf1, bef1, Wf2, bf2, gf2, bef2, Wf3, bf3, out);
}

// round 4
// speedup vs baseline: 1.0403x; 1.0403x over previous
#include <cuda_runtime.h>
#include <math.h>

#define BB 8
#define NN 2048
#define NP (BB*NN)      // 16384 points
#define DD 64
#define KK 8
#define LL 3
#define H1 256
#define H2 128

// ---- scratch (device globals; no allocation allowed) ----
__device__ float g_feat[NP*DD];       // 4 MB
__device__ float g_fw[NP*LL];         // 192 KB
__device__ int   g_idx[NP*KK];        // 512 KB
__device__ float g_fcfn[NP*2*DD];     // 8 MB  (per point: [fc(64) | fn(64)])
__device__ float g_agg[NP*DD];        // 4 MB
__device__ float g_pd[NP*4*KK];       // 2 MB  KNN partial dists, layout [(s*8+k)*NP + p]
__device__ int   g_pi[NP*4*KK];       // 2 MB  KNN partial idx

__device__ __forceinline__ float leaky_f(float v) { return v > 0.f ? v : 0.2f*v; }

// ---- packed f32x2 helpers (FFMA2 reachable only via explicit PTX) ----
__device__ __forceinline__ unsigned long long fma2(unsigned long long a,
                                                   unsigned long long b,
                                                   unsigned long long c) {
    unsigned long long d;
    asm("fma.rn.f32x2 %0, %1, %2, %3;" : "=l"(d) : "l"(a), "l"(b), "l"(c));
    return d;
}
__device__ __forceinline__ unsigned long long pack2(float lo, float hi) {
    unsigned long long r;
    asm("mov.b64 %0, {%1, %2};" : "=l"(r) : "f"(lo), "f"(hi));
    return r;
}
__device__ __forceinline__ float2 unpack2(unsigned long long v) {
    float lo, hi;
    asm("mov.b64 {%0, %1}, %2;" : "=f"(lo), "=f"(hi) : "l"(v));
    return make_float2(lo, hi);
}

// ============================================================
// Kernel 1: warp-per-point.
// feat = leaky((x@W1+b1)*g1+be1); fw = sigmoid(relu(x@Ws1+bs1)@Ws2+bs2)
// 128 thr/block = 4 points; lane handles d and d+32.
// ============================================================
__global__ __launch_bounds__(128)
void k_feat(const float* __restrict__ x,
            const float* __restrict__ W1, const float* __restrict__ b1,
            const float* __restrict__ g1, const float* __restrict__ be1,
            const float* __restrict__ Ws1, const float* __restrict__ bs1,
            const float* __restrict__ Ws2, const float* __restrict__ bs2)
{
    int lane = threadIdx.x & 31;
    int p = blockIdx.x * 4 + (threadIdx.x >> 5);
    float x0 = x[p*3+0], x1 = x[p*3+1], x2 = x[p*3+2];

    float a0 = 0.f, a1 = 0.f, a2 = 0.f;
    #pragma unroll
    for (int h = 0; h < 2; ++h) {
        int d = lane + 32*h;
        float v = fmaf(x2, W1[128+d], fmaf(x1, W1[64+d], fmaf(x0, W1[d], b1[d])));
        v = v * g1[d] + be1[d];
        g_feat[(size_t)p*DD + d] = leaky_f(v);

        float hv = fmaf(x2, Ws1[128+d], fmaf(x1, Ws1[64+d], fmaf(x0, Ws1[d], bs1[d])));
        hv = hv > 0.f ? hv : 0.f;
        a0 = fmaf(hv, Ws2[d*3+0], a0);
        a1 = fmaf(hv, Ws2[d*3+1], a1);
        a2 = fmaf(hv, Ws2[d*3+2], a2);
    }
    #pragma unroll
    for (int off = 16; off > 0; off >>= 1) {
        a0 += __shfl_xor_sync(0xFFFFFFFF, a0, off);
        a1 += __shfl_xor_sync(0xFFFFFFFF, a1, off);
        a2 += __shfl_xor_sync(0xFFFFFFFF, a2, off);
    }
    if (lane == 0) {
        g_fw[p*3+0] = 1.f/(1.f + expf(-a0));
        g_fw[p*3+1] = 1.f/(1.f + expf(-a1));
        g_fw[p*3+2] = 1.f/(1.f + expf(-a2));
    }
}

// ============================================================
// Kernel 2a: KNN partial — 4 slices of 512 candidates each.
// block = 128 points, slice s. grid = BB*16*4 = 512 blocks.
// ============================================================
__global__ __launch_bounds__(128)
void k_knn_part(const float* __restrict__ x)
{
    __shared__ float4 xs[512];
    int tid = threadIdx.x;
    int s   = blockIdx.x & 3;
    int t   = (blockIdx.x >> 2) & 15;
    int b   = blockIdx.x >> 6;
    const float* xb = x + (size_t)b * NN * 3;
    int m0 = s * 512;

    for (int i = tid; i < 512; i += 128) {
        int m = m0 + i;
        float a0 = xb[m*3+0], a1 = xb[m*3+1], a2 = xb[m*3+2];
        xs[i] = make_float4(a0, a1, a2, a0*a0 + a1*a1 + a2*a2);
    }
    __syncthreads();

    int n = t*128 + tid;
    float c0 = xb[n*3+0], c1 = xb[n*3+1], c2 = xb[n*3+2];
    float cw = c0*c0 + c1*c1 + c2*c2;

    float bd[KK]; int bi[KK];
    #pragma unroll
    for (int k = 0; k < KK; ++k) { bd[k] = 3.4e38f; bi[k] = 0; }

    #pragma unroll 4
    for (int i = 0; i < 512; ++i) {
        float4 q = xs[i];
        float d2 = cw + q.w - 2.f*(c0*q.x + c1*q.y + c2*q.z);
        if (d2 < bd[KK-1]) {
            float v = d2; int vi = m0 + i;
            #pragma unroll
            for (int k = 0; k < KK; ++k) {
                if (v < bd[k]) {
                    float td = bd[k]; int ti = bi[k];
                    bd[k] = v; bi[k] = vi; v = td; vi = ti;
                }
            }
        }
    }
    int p = b*NN + n;
    #pragma unroll
    for (int k = 0; k < KK; ++k) {
        g_pd[(size_t)(s*KK + k)*NP + p] = bd[k];
        g_pi[(size_t)(s*KK + k)*NP + p] = bi[k];
    }
}

// ============================================================
// Kernel 2b: KNN merge — 32 candidates -> top 8 per point.
// ============================================================
__global__ __launch_bounds__(256)
void k_knn_merge()
{
    int p = blockIdx.x * 256 + threadIdx.x;
    float bd[KK]; int bi[KK];
    #pragma unroll
    for (int k = 0; k < KK; ++k) { bd[k] = 3.4e38f; bi[k] = 0; }

    #pragma unroll
    for (int s = 0; s < 4; ++s) {
        #pragma unroll
        for (int k2 = 0; k2 < KK; ++k2) {
            float v  = g_pd[(size_t)(s*KK + k2)*NP + p];
            int   vi = g_pi[(size_t)(s*KK + k2)*NP + p];
            if (v < bd[KK-1]) {
                #pragma unroll
                for (int k = 0; k < KK; ++k) {
                    if (v < bd[k]) {
                        float td = bd[k]; int ti = bi[k];
                        bd[k] = v; bi[k] = vi; v = td; vi = ti;
                    }
                }
            }
        }
    }
    #pragma unroll
    for (int k = 0; k < KK; ++k) g_idx[(size_t)p*KK + k] = bi[k];
}

// ============================================================
// Kernel 3: [fc|fn] = feat @ [W2[:64] | W2[64:]]  ([16384,64] x [64,128])
// 128 thr/block, 32 points/block, FFMA2 mainloop.
// ============================================================
__global__ __launch_bounds__(128)
void k_fcfn(const float* __restrict__ W2)
{
    __shared__ __align__(16) float fs[64*36];   // feat^T tile (rows 144B, 16B-aligned)
    __shared__ float ws[64*128];
    int tid = threadIdx.x;
    int pb  = blockIdx.x * 32;

    for (int i = tid; i < 32*64; i += 128) {
        int p = i >> 6, c = i & 63;
        fs[c*36 + p] = g_feat[(size_t)(pb+p)*DD + c];
    }
    for (int i = tid; i < 64*128; i += 128) {
        int c = i >> 7, j = i & 127;
        ws[i] = (j < 64) ? W2[c*64 + j] : W2[(64+c)*64 + (j-64)];
    }
    __syncthreads();

    int j = tid;
    unsigned long long acc2[16];
    unsigned long long z = pack2(0.f, 0.f);
    #pragma unroll
    for (int q = 0; q < 16; ++q) acc2[q] = z;

    #pragma unroll 4
    for (int c = 0; c < 64; ++c) {
        float w = ws[c*128 + j];
        unsigned long long ww = pack2(w, w);
        const ulonglong2* f2 = (const ulonglong2*)(fs + c*36);
        #pragma unroll
        for (int q = 0; q < 8; ++q) {
            ulonglong2 u = f2[q];
            acc2[2*q+0] = fma2(u.x, ww, acc2[2*q+0]);
            acc2[2*q+1] = fma2(u.y, ww, acc2[2*q+1]);
        }
    }
    #pragma unroll
    for (int q = 0; q < 16; ++q) {
        float2 v = unpack2(acc2[q]);
        g_fcfn[(size_t)(pb + 2*q+0)*128 + j] = v.x;
        g_fcfn[(size_t)(pb + 2*q+1)*128 + j] = v.y;
    }
}

// ============================================================
// Kernel 4: conv = leaky((fc + fn[neighbor] + b2)*g2 + be2); agg = max over k
// thread per (point, 4 d's), float4 everywhere.
// ============================================================
__global__ __launch_bounds__(256)
void k_edge(const float* __restrict__ b2,
            const float* __restrict__ g2,
            const float* __restrict__ be2)
{
    int g = blockIdx.x * 256 + threadIdx.x;   // NP*16 threads
    int p = g >> 4, d4 = (g & 15) * 4;
    int b = p >> 11;

    float4 fc = *(const float4*)&g_fcfn[(size_t)p*128 + d4];
    float4 Bv = *(const float4*)&b2[d4];
    float4 Gv = *(const float4*)&g2[d4];
    float4 Ev = *(const float4*)&be2[d4];
    float bx = fc.x + Bv.x, by = fc.y + Bv.y, bz = fc.z + Bv.z, bw = fc.w + Bv.w;

    int m[KK];
    const int* ip = g_idx + (size_t)p*KK;
    #pragma unroll
    for (int k = 0; k < KK; ++k) m[k] = ip[k];

    size_t rowb = (size_t)(b << 11) * 128 + 64 + d4;
    float mx0 = -3.4e38f, mx1 = -3.4e38f, mx2 = -3.4e38f, mx3 = -3.4e38f;
    #pragma unroll
    for (int k = 0; k < KK; ++k) {
        float4 fn = *(const float4*)&g_fcfn[rowb + (size_t)m[k]*128];
        mx0 = fmaxf(mx0, leaky_f((bx + fn.x) * Gv.x + Ev.x));
        mx1 = fmaxf(mx1, leaky_f((by + fn.y) * Gv.y + Ev.y));
        mx2 = fmaxf(mx2, leaky_f((bz + fn.z) * Gv.z + Ev.z));
        mx3 = fmaxf(mx3, leaky_f((bw + fn.w) * Gv.w + Ev.w));
    }
    *(float4*)&g_agg[(size_t)p*DD + d4] = make_float4(mx0, mx1, mx2, mx3);
}

// ============================================================
// Kernel 5: fusion MLP, TP=32 points/block, FFMA2 mainloops.
// dynamic smem: h1 (256*36) + region (192*36, multi then overlaid by h2).
// ============================================================
#define TP 32
#define PP 36
#define FUSION_SMEM ((256*PP + 192*PP) * 4)   // 64512 B

__global__ __launch_bounds__(256)
void k_fusion(const float* __restrict__ x,
              const float* __restrict__ Wf1, const float* __restrict__ bf1,
              const float* __restrict__ gf1, const float* __restrict__ bef1,
              const float* __restrict__ Wf2, const float* __restrict__ bf2,
              const float* __restrict__ gf2, const float* __restrict__ bef2,
              const float* __restrict__ Wf3, const float* __restrict__ bf3,
              float* __restrict__ out)
{
    extern __shared__ __align__(16) float smem[];
    float* h1_s    = smem;               // 256*PP
    float* multi_s = smem + 256*PP;      // 192*PP
    float* h2_s    = multi_s;            // overlay: multi dead after phase B

    int tid = threadIdx.x;
    int pb  = blockIdx.x * TP;

    // Phase A: multi[kk][p] = agg[p][kk&63] * fw[p][kk>>6]
    for (int i = tid; i < TP*192; i += 256) {
        int p = i / 192, kk = i - p*192;
        multi_s[kk*PP + p] = g_agg[(size_t)(pb+p)*DD + (kk & 63)]
                           * g_fw[(size_t)(pb+p)*3 + (kk >> 6)];
    }
    __syncthreads();

    // Phase B: h1 = leaky((multi@Wf1 + bf1)*gf1 + bef1); thread per col j.
    {
        int j = tid;
        unsigned long long acc2[16];
        unsigned long long z = pack2(0.f, 0.f);
        #pragma unroll
        for (int q = 0; q < 16; ++q) acc2[q] = z;

        #pragma unroll 2
        for (int kk = 0; kk < 192; ++kk) {
            float w = Wf1[kk*256 + j];
            unsigned long long ww = pack2(w, w);
            const ulonglong2* m2 = (const ulonglong2*)(multi_s + kk*PP);
            #pragma unroll
            for (int q = 0; q < 8; ++q) {
                ulonglong2 u = m2[q];
                acc2[2*q+0] = fma2(u.x, ww, acc2[2*q+0]);
                acc2[2*q+1] = fma2(u.y, ww, acc2[2*q+1]);
            }
        }
        float bj = bf1[j], gj = gf1[j], bej = bef1[j];
        #pragma unroll
        for (int q = 0; q < 16; ++q) {
            float2 v = unpack2(acc2[q]);
            h1_s[j*PP + 2*q+0] = leaky_f((v.x + bj) * gj + bej);
            h1_s[j*PP + 2*q+1] = leaky_f((v.y + bj) * gj + bej);
        }
    }
    __syncthreads();

    // Phase C: h2 (128 cols, 2 threads per col over 16-point halves)
    {
        int j  = tid & 127;
        int ph = (tid >> 7) * 16;
        unsigned long long acc2[8];
        unsigned long long z = pack2(0.f, 0.f);
        #pragma unroll
        for (int q = 0; q < 8; ++q) acc2[q] = z;

        #pragma unroll 2
        for (int kk = 0; kk < 256; ++kk) {
            float w = Wf2[kk*128 + j];
            unsigned long long ww = pack2(w, w);
            const ulonglong2* h2p = (const ulonglong2*)(h1_s + kk*PP + ph);
            #pragma unroll
            for (int q = 0; q < 4; ++q) {
                ulonglong2 u = h2p[q];
                acc2[2*q+0] = fma2(u.x, ww, acc2[2*q+0]);
                acc2[2*q+1] = fma2(u.y, ww, acc2[2*q+1]);
            }
        }
        float bj = bf2[j], gj = gf2[j], bej = bef2[j];
        #pragma unroll
        for (int q = 0; q < 8; ++q) {
            float2 v = unpack2(acc2[q]);
            h2_s[j*PP + ph + 2*q+0] = leaky_f((v.x + bj) * gj + bej);
            h2_s[j*PP + ph + 2*q+1] = leaky_f((v.y + bj) * gj + bej);
        }
    }
    __syncthreads();

    // Phase D: delta + residual (TP*3 = 96 outputs)
    if (tid < TP*3) {
        int p = tid / 3, c = tid - p*3;
        float acc = 0.f;
        #pragma unroll 4
        for (int kk = 0; kk < 128; ++kk)
            acc = fmaf(h2_s[kk*PP + p], Wf3[kk*3 + c], acc);
        size_t o = (size_t)(pb+p)*3 + c;
        out[o] = x[o] + 0.1f * (acc + bf3[c]);
    }
}

// ============================================================
extern "C" void kernel_launch(void* const* d_in, const int* in_sizes, int n_in,
                              void* d_out, int out_size)
{
    const float* x   = (const float*)d_in[0];
    const float* W1  = (const float*)d_in[1];
    const float* b1  = (const float*)d_in[2];
    const float* g1  = (const float*)d_in[3];
    const float* be1 = (const float*)d_in[4];
    const float* W2  = (const float*)d_in[5];
    const float* b2  = (const float*)d_in[6];
    const float* g2  = (const float*)d_in[7];
    const float* be2 = (const float*)d_in[8];
    const float* Ws1 = (const float*)d_in[9];
    const float* bs1 = (const float*)d_in[10];
    const float* Ws2 = (const float*)d_in[11];
    const float* bs2 = (const float*)d_in[12];
    const float* Wf1 = (const float*)d_in[13];
    const float* bf1 = (const float*)d_in[14];
    const float* gf1 = (const float*)d_in[15];
    const float* bef1= (const float*)d_in[16];
    const float* Wf2 = (const float*)d_in[17];
    const float* bf2 = (const float*)d_in[18];
    const float* gf2 = (const float*)d_in[19];
    const float* bef2= (const float*)d_in[20];
    const float* Wf3 = (const float*)d_in[21];
    const float* bf3 = (const float*)d_in[22];
    float* out = (float*)d_out;

    cudaFuncSetAttribute(k_fusion, cudaFuncAttributeMaxDynamicSharedMemorySize,
                         FUSION_SMEM);

    k_feat<<<NP/4, 128>>>(x, W1, b1, g1, be1, Ws1, bs1, Ws2, bs2);
    k_knn_part<<<BB*16*4, 128>>>(x);
    k_knn_merge<<<NP/256, 256>>>();
    k_fcfn<<<NP/32, 128>>>(W2);
    k_edge<<<(NP*16)/256, 256>>>(b2, g2, be2);
    k_fusion<<<NP/TP, 256, FUSION_SMEM>>>(x, Wf1, bf1, gf1, bef1,
                                          Wf2, bf2, gf2, bef2, Wf3, bf3, out);
}

// round 5
// speedup vs baseline: 1.2807x; 1.2311x over previous
#include <cuda_runtime.h>
#include <math.h>

#define BB 8
#define NN 2048
#define NP (BB*NN)      // 16384 points
#define DD 64
#define KK 8
#define LL 3
#define H1 256
#define H2 128

// ---- scratch (device globals; no allocation allowed) ----
__device__ float g_feat[NP*DD];       // 4 MB
__device__ float g_fw[NP*LL];         // 192 KB
__device__ int   g_idx[NP*KK];        // 512 KB
__device__ float g_fcfn[NP*2*DD];     // 8 MB  (per point: [fc(64) | fn(64)])
__device__ float g_agg[NP*DD];        // 4 MB
__device__ float g_pd[NP*4*KK];       // 2 MB
__device__ int   g_pi[NP*4*KK];       // 2 MB

__device__ __forceinline__ float leaky_f(float v) { return v > 0.f ? v : 0.2f*v; }

// ---- packed f32x2 helpers ----
__device__ __forceinline__ unsigned long long fma2(unsigned long long a,
                                                   unsigned long long b,
                                                   unsigned long long c) {
    unsigned long long d;
    asm("fma.rn.f32x2 %0, %1, %2, %3;" : "=l"(d) : "l"(a), "l"(b), "l"(c));
    return d;
}
__device__ __forceinline__ unsigned long long pack2(float lo, float hi) {
    unsigned long long r;
    asm("mov.b64 %0, {%1, %2};" : "=l"(r) : "f"(lo), "f"(hi));
    return r;
}
__device__ __forceinline__ float2 unpack2(unsigned long long v) {
    float lo, hi;
    asm("mov.b64 {%0, %1}, %2;" : "=f"(lo), "=f"(hi) : "l"(v));
    return make_float2(lo, hi);
}

// ============================================================
// Kernel 1: warp-per-point feat + suppressor (unchanged)
// ============================================================
__global__ __launch_bounds__(128)
void k_feat(const float* __restrict__ x,
            const float* __restrict__ W1, const float* __restrict__ b1,
            const float* __restrict__ g1, const float* __restrict__ be1,
            const float* __restrict__ Ws1, const float* __restrict__ bs1,
            const float* __restrict__ Ws2, const float* __restrict__ bs2)
{
    int lane = threadIdx.x & 31;
    int p = blockIdx.x * 4 + (threadIdx.x >> 5);
    float x0 = x[p*3+0], x1 = x[p*3+1], x2 = x[p*3+2];

    float a0 = 0.f, a1 = 0.f, a2 = 0.f;
    #pragma unroll
    for (int h = 0; h < 2; ++h) {
        int d = lane + 32*h;
        float v = fmaf(x2, W1[128+d], fmaf(x1, W1[64+d], fmaf(x0, W1[d], b1[d])));
        v = v * g1[d] + be1[d];
        g_feat[(size_t)p*DD + d] = leaky_f(v);

        float hv = fmaf(x2, Ws1[128+d], fmaf(x1, Ws1[64+d], fmaf(x0, Ws1[d], bs1[d])));
        hv = hv > 0.f ? hv : 0.f;
        a0 = fmaf(hv, Ws2[d*3+0], a0);
        a1 = fmaf(hv, Ws2[d*3+1], a1);
        a2 = fmaf(hv, Ws2[d*3+2], a2);
    }
    #pragma unroll
    for (int off = 16; off > 0; off >>= 1) {
        a0 += __shfl_xor_sync(0xFFFFFFFF, a0, off);
        a1 += __shfl_xor_sync(0xFFFFFFFF, a1, off);
        a2 += __shfl_xor_sync(0xFFFFFFFF, a2, off);
    }
    if (lane == 0) {
        g_fw[p*3+0] = 1.f/(1.f + expf(-a0));
        g_fw[p*3+1] = 1.f/(1.f + expf(-a1));
        g_fw[p*3+2] = 1.f/(1.f + expf(-a2));
    }
}

// ============================================================
// Kernel 2a: KNN partial — 4 slices of 512 candidates (unchanged)
// ============================================================
__global__ __launch_bounds__(128)
void k_knn_part(const float* __restrict__ x)
{
    __shared__ float4 xs[512];
    int tid = threadIdx.x;
    int s   = blockIdx.x & 3;
    int t   = (blockIdx.x >> 2) & 15;
    int b   = blockIdx.x >> 6;
    const float* xb = x + (size_t)b * NN * 3;
    int m0 = s * 512;

    for (int i = tid; i < 512; i += 128) {
        int m = m0 + i;
        float a0 = xb[m*3+0], a1 = xb[m*3+1], a2 = xb[m*3+2];
        xs[i] = make_float4(a0, a1, a2, a0*a0 + a1*a1 + a2*a2);
    }
    __syncthreads();

    int n = t*128 + tid;
    float c0 = xb[n*3+0], c1 = xb[n*3+1], c2 = xb[n*3+2];
    float cw = c0*c0 + c1*c1 + c2*c2;

    float bd[KK]; int bi[KK];
    #pragma unroll
    for (int k = 0; k < KK; ++k) { bd[k] = 3.4e38f; bi[k] = 0; }

    #pragma unroll 4
    for (int i = 0; i < 512; ++i) {
        float4 q = xs[i];
        float d2 = cw + q.w - 2.f*(c0*q.x + c1*q.y + c2*q.z);
        if (d2 < bd[KK-1]) {
            float v = d2; int vi = m0 + i;
            #pragma unroll
            for (int k = 0; k < KK; ++k) {
                if (v < bd[k]) {
                    float td = bd[k]; int ti = bi[k];
                    bd[k] = v; bi[k] = vi; v = td; vi = ti;
                }
            }
        }
    }
    int p = b*NN + n;
    #pragma unroll
    for (int k = 0; k < KK; ++k) {
        g_pd[(size_t)(s*KK + k)*NP + p] = bd[k];
        g_pi[(size_t)(s*KK + k)*NP + p] = bi[k];
    }
}

// ============================================================
// Kernel 2b: KNN merge (unchanged)
// ============================================================
__global__ __launch_bounds__(256)
void k_knn_merge()
{
    int p = blockIdx.x * 256 + threadIdx.x;
    float bd[KK]; int bi[KK];
    #pragma unroll
    for (int k = 0; k < KK; ++k) { bd[k] = 3.4e38f; bi[k] = 0; }

    #pragma unroll
    for (int s = 0; s < 4; ++s) {
        #pragma unroll
        for (int k2 = 0; k2 < KK; ++k2) {
            float v  = g_pd[(size_t)(s*KK + k2)*NP + p];
            int   vi = g_pi[(size_t)(s*KK + k2)*NP + p];
            if (v < bd[KK-1]) {
                #pragma unroll
                for (int k = 0; k < KK; ++k) {
                    if (v < bd[k]) {
                        float td = bd[k]; int ti = bi[k];
                        bd[k] = v; bi[k] = vi; v = td; vi = ti;
                    }
                }
            }
        }
    }
    #pragma unroll
    for (int k = 0; k < KK; ++k) g_idx[(size_t)p*KK + k] = bi[k];
}

// ============================================================
// Kernel 3 v2: [fc|fn] = feat @ W2cat. 256 thr, 32 pts/block.
// Micro-tile 4p x 4c per thread: 1 A-LDS.128 + 1 B-LDS.128 per 8 FFMA2.
// ============================================================
__global__ __launch_bounds__(256)
void k_fcfn(const float* __restrict__ W2)
{
    __shared__ __align__(16) float fs[64*36];   // [c*36 + p]
    __shared__ __align__(16) float ws[64*128];  // [c*128 + j]
    int tid = threadIdx.x;
    int pb  = blockIdx.x * 32;

    for (int i = tid; i < 32*64; i += 256) {
        int p = i >> 6, c = i & 63;
        fs[c*36 + p] = g_feat[(size_t)(pb+p)*DD + c];
    }
    for (int i = tid; i < 64*128; i += 256) {
        int c = i >> 7, j = i & 127;
        ws[i] = (j < 64) ? W2[c*64 + j] : W2[(64+c)*64 + (j-64)];
    }
    __syncthreads();

    int tp = tid >> 5, tc = tid & 31;
    int p0 = tp * 4, j0 = tc * 4;

    unsigned long long acc[8];          // [pp*2+cp]: cols (j0+2cp, j0+2cp+1)
    unsigned long long z = pack2(0.f, 0.f);
    #pragma unroll
    for (int q = 0; q < 8; ++q) acc[q] = z;

    #pragma unroll 8
    for (int c = 0; c < 64; ++c) {
        float4 a = *(const float4*)&fs[c*36 + p0];           // broadcast
        ulonglong2 b = *(const ulonglong2*)&ws[c*128 + j0];  // conflict-free
        unsigned long long a0 = pack2(a.x, a.x);
        unsigned long long a1 = pack2(a.y, a.y);
        unsigned long long a2 = pack2(a.z, a.z);
        unsigned long long a3 = pack2(a.w, a.w);
        acc[0] = fma2(a0, b.x, acc[0]); acc[1] = fma2(a0, b.y, acc[1]);
        acc[2] = fma2(a1, b.x, acc[2]); acc[3] = fma2(a1, b.y, acc[3]);
        acc[4] = fma2(a2, b.x, acc[4]); acc[5] = fma2(a2, b.y, acc[5]);
        acc[6] = fma2(a3, b.x, acc[6]); acc[7] = fma2(a3, b.y, acc[7]);
    }
    #pragma unroll
    for (int pp = 0; pp < 4; ++pp) {
        float2 v0 = unpack2(acc[pp*2+0]);
        float2 v1 = unpack2(acc[pp*2+1]);
        *(float4*)&g_fcfn[(size_t)(pb + p0 + pp)*128 + j0] =
            make_float4(v0.x, v0.y, v1.x, v1.y);
    }
}

// ============================================================
// Kernel 4: edge conv + max-agg (unchanged)
// ============================================================
__global__ __launch_bounds__(256)
void k_edge(const float* __restrict__ b2,
            const float* __restrict__ g2,
            const float* __restrict__ be2)
{
    int g = blockIdx.x * 256 + threadIdx.x;
    int p = g >> 4, d4 = (g & 15) * 4;
    int b = p >> 11;

    float4 fc = *(const float4*)&g_fcfn[(size_t)p*128 + d4];
    float4 Bv = *(const float4*)&b2[d4];
    float4 Gv = *(const float4*)&g2[d4];
    float4 Ev = *(const float4*)&be2[d4];
    float bx = fc.x + Bv.x, by = fc.y + Bv.y, bz = fc.z + Bv.z, bw = fc.w + Bv.w;

    int m[KK];
    const int* ip = g_idx + (size_t)p*KK;
    #pragma unroll
    for (int k = 0; k < KK; ++k) m[k] = ip[k];

    size_t rowb = (size_t)(b << 11) * 128 + 64 + d4;
    float mx0 = -3.4e38f, mx1 = -3.4e38f, mx2 = -3.4e38f, mx3 = -3.4e38f;
    #pragma unroll
    for (int k = 0; k < KK; ++k) {
        float4 fn = *(const float4*)&g_fcfn[rowb + (size_t)m[k]*128];
        mx0 = fmaxf(mx0, leaky_f((bx + fn.x) * Gv.x + Ev.x));
        mx1 = fmaxf(mx1, leaky_f((by + fn.y) * Gv.y + Ev.y));
        mx2 = fmaxf(mx2, leaky_f((bz + fn.z) * Gv.z + Ev.z));
        mx3 = fmaxf(mx3, leaky_f((bw + fn.w) * Gv.w + Ev.w));
    }
    *(float4*)&g_agg[(size_t)p*DD + d4] = make_float4(mx0, mx1, mx2, mx3);
}

// ============================================================
// Kernel 5 v2: fusion MLP. 256 thr, TP=32 pts/block.
// Register micro-tiles; weights staged in 32KB smem chunks.
//   multi: [kk*36 + p]  (col-major, broadcast A reads)
//   h1:    [p*264 + j]  (point-major, conflict-free f4 stores, broadcast reads)
//   h2:    [p*132 + j]  (overlays multi region)
// ============================================================
#define TP 32
#define PPA 36
#define H1P 264
#define H2P 132
#define WS_F      8192                        // ws: 32x256 floats
#define MULTI_OFF WS_F                        // 192*36 = 6912 floats
#define H1_OFF    (WS_F + 192*PPA)            // 15104
#define FUSION_SMEM ((WS_F + 192*PPA + TP*H1P) * 4)   // 94208 B

__global__ __launch_bounds__(256)
void k_fusion(const float* __restrict__ x,
              const float* __restrict__ Wf1, const float* __restrict__ bf1,
              const float* __restrict__ gf1, const float* __restrict__ bef1,
              const float* __restrict__ Wf2, const float* __restrict__ bf2,
              const float* __restrict__ gf2, const float* __restrict__ bef2,
              const float* __restrict__ Wf3, const float* __restrict__ bf3,
              float* __restrict__ out)
{
    extern __shared__ __align__(16) float smem[];
    float* ws      = smem;                 // staged weight chunks (32KB)
    float* multi_s = smem + MULTI_OFF;     // [kk*36 + p]
    float* h2_s    = multi_s;              // overlay: [p*132 + j]
    float* h1_s    = smem + H1_OFF;        // [p*264 + j]

    int tid = threadIdx.x;
    int pb  = blockIdx.x * TP;
    int tp  = tid >> 5, tc = tid & 31;
    int p0  = tp * 4;
    unsigned long long z = pack2(0.f, 0.f);

    // Phase A: build multi
    for (int i = tid; i < TP*192; i += 256) {
        int p = i / 192, kk = i - p*192;
        multi_s[kk*PPA + p] = g_agg[(size_t)(pb+p)*DD + (kk & 63)]
                            * g_fw[(size_t)(pb+p)*3 + (kk >> 6)];
    }

    // ---- Layer 1: 192 -> 256, thread tile 4p x 8c (j0 = tc*8) ----
    {
        int j0 = tc * 8;
        unsigned long long acc[16];        // [pp*4+cp]
        #pragma unroll
        for (int q = 0; q < 16; ++q) acc[q] = z;

        for (int kc = 0; kc < 192; kc += 32) {
            __syncthreads();
            const float4* src = (const float4*)(Wf1 + kc*256);
            float4* dst = (float4*)ws;
            #pragma unroll
            for (int i = tid; i < 2048; i += 256) dst[i] = src[i];
            __syncthreads();

            #pragma unroll 8
            for (int r = 0; r < 32; ++r) {
                float4 a = *(const float4*)&multi_s[(kc+r)*PPA + p0];
                const ulonglong2* bp = (const ulonglong2*)&ws[r*256 + j0];
                ulonglong2 b0 = bp[0], b1 = bp[1];
                unsigned long long a0 = pack2(a.x, a.x);
                unsigned long long a1 = pack2(a.y, a.y);
                unsigned long long a2 = pack2(a.z, a.z);
                unsigned long long a3 = pack2(a.w, a.w);
                acc[0]  = fma2(a0, b0.x, acc[0]);  acc[1]  = fma2(a0, b0.y, acc[1]);
                acc[2]  = fma2(a0, b1.x, acc[2]);  acc[3]  = fma2(a0, b1.y, acc[3]);
                acc[4]  = fma2(a1, b0.x, acc[4]);  acc[5]  = fma2(a1, b0.y, acc[5]);
                acc[6]  = fma2(a1, b1.x, acc[6]);  acc[7]  = fma2(a1, b1.y, acc[7]);
                acc[8]  = fma2(a2, b0.x, acc[8]);  acc[9]  = fma2(a2, b0.y, acc[9]);
                acc[10] = fma2(a2, b1.x, acc[10]); acc[11] = fma2(a2, b1.y, acc[11]);
                acc[12] = fma2(a3, b0.x, acc[12]); acc[13] = fma2(a3, b0.y, acc[13]);
                acc[14] = fma2(a3, b1.x, acc[14]); acc[15] = fma2(a3, b1.y, acc[15]);
            }
        }

        // epilogue: BN + leaky -> h1 (point-major, float4 stores)
        float4 B0 = *(const float4*)&bf1[j0],  B1 = *(const float4*)&bf1[j0+4];
        float4 G0 = *(const float4*)&gf1[j0],  G1 = *(const float4*)&gf1[j0+4];
        float4 E0 = *(const float4*)&bef1[j0], E1 = *(const float4*)&bef1[j0+4];
        #pragma unroll
        for (int pp = 0; pp < 4; ++pp) {
            float2 v0 = unpack2(acc[pp*4+0]);
            float2 v1 = unpack2(acc[pp*4+1]);
            float2 v2 = unpack2(acc[pp*4+2]);
            float2 v3 = unpack2(acc[pp*4+3]);
            float4 o0 = make_float4(
                leaky_f((v0.x + B0.x)*G0.x + E0.x),
                leaky_f((v0.y + B0.y)*G0.y + E0.y),
                leaky_f((v1.x + B0.z)*G0.z + E0.z),
                leaky_f((v1.y + B0.w)*G0.w + E0.w));
            float4 o1 = make_float4(
                leaky_f((v2.x + B1.x)*G1.x + E1.x),
                leaky_f((v2.y + B1.y)*G1.y + E1.y),
                leaky_f((v3.x + B1.z)*G1.z + E1.z),
                leaky_f((v3.y + B1.w)*G1.w + E1.w));
            float* hrow = h1_s + (size_t)(p0+pp)*H1P + j0;
            *(float4*)(hrow)     = o0;
            *(float4*)(hrow + 4) = o1;
        }
    }
    __syncthreads();   // h1 complete; multi reads done -> h2 overlay safe

    // ---- Layer 2: 256 -> 128, thread tile 4p x 4c (j0 = tc*4) ----
    {
        int j0 = tc * 4;
        unsigned long long acc[8];         // [pp*2+cp]
        #pragma unroll
        for (int q = 0; q < 8; ++q) acc[q] = z;

        for (int kc = 0; kc < 256; kc += 32) {
            __syncthreads();
            const float4* src = (const float4*)(Wf2 + kc*128);
            float4* dst = (float4*)ws;
            #pragma unroll
            for (int i = tid; i < 1024; i += 256) dst[i] = src[i];
            __syncthreads();

            #pragma unroll 8
            for (int r = 0; r < 32; ++r) {
                float a0f = h1_s[(size_t)(p0+0)*H1P + kc + r];
                float a1f = h1_s[(size_t)(p0+1)*H1P + kc + r];
                float a2f = h1_s[(size_t)(p0+2)*H1P + kc + r];
                float a3f = h1_s[(size_t)(p0+3)*H1P + kc + r];
                ulonglong2 b = *(const ulonglong2*)&ws[r*128 + j0];
                unsigned long long a0 = pack2(a0f, a0f);
                unsigned long long a1 = pack2(a1f, a1f);
                unsigned long long a2 = pack2(a2f, a2f);
                unsigned long long a3 = pack2(a3f, a3f);
                acc[0] = fma2(a0, b.x, acc[0]); acc[1] = fma2(a0, b.y, acc[1]);
                acc[2] = fma2(a1, b.x, acc[2]); acc[3] = fma2(a1, b.y, acc[3]);
                acc[4] = fma2(a2, b.x, acc[4]); acc[5] = fma2(a2, b.y, acc[5]);
                acc[6] = fma2(a3, b.x, acc[6]); acc[7] = fma2(a3, b.y, acc[7]);
            }
        }

        // epilogue: BN + leaky -> h2 (point-major float4 stores)
        float4 B0 = *(const float4*)&bf2[j0];
        float4 G0 = *(const float4*)&gf2[j0];
        float4 E0 = *(const float4*)&bef2[j0];
        #pragma unroll
        for (int pp = 0; pp < 4; ++pp) {
            float2 v0 = unpack2(acc[pp*2+0]);
            float2 v1 = unpack2(acc[pp*2+1]);
            float4 o = make_float4(
                leaky_f((v0.x + B0.x)*G0.x + E0.x),
                leaky_f((v0.y + B0.y)*G0.y + E0.y),
                leaky_f((v1.x + B0.z)*G0.z + E0.z),
                leaky_f((v1.y + B0.w)*G0.w + E0.w));
            *(float4*)&h2_s[(size_t)(p0+pp)*H2P + j0] = o;
        }
    }
    __syncthreads();

    // ---- Layer 3 + residual (96 outputs) ----
    if (tid < TP*3) {
        int p = tid / 3, c = tid - p*3;
        float acc = 0.f;
        #pragma unroll 4
        for (int kk = 0; kk < 128; ++kk)
            acc = fmaf(h2_s[(size_t)p*H2P + kk], Wf3[kk*3 + c], acc);
        size_t o = (size_t)(pb+p)*3 + c;
        out[o] = x[o] + 0.1f * (acc + bf3[c]);
    }
}

// ============================================================
extern "C" void kernel_launch(void* const* d_in, const int* in_sizes, int n_in,
                              void* d_out, int out_size)
{
    const float* x   = (const float*)d_in[0];
    const float* W1  = (const float*)d_in[1];
    const float* b1  = (const float*)d_in[2];
    const float* g1  = (const float*)d_in[3];
    const float* be1 = (const float*)d_in[4];
    const float* W2  = (const float*)d_in[5];
    const float* b2  = (const float*)d_in[6];
    const float* g2  = (const float*)d_in[7];
    const float* be2 = (const float*)d_in[8];
    const float* Ws1 = (const float*)d_in[9];
    const float* bs1 = (const float*)d_in[10];
    const float* Ws2 = (const float*)d_in[11];
    const float* bs2 = (const float*)d_in[12];
    const float* Wf1 = (const float*)d_in[13];
    const float* bf1 = (const float*)d_in[14];
    const float* gf1 = (const float*)d_in[15];
    const float* bef1= (const float*)d_in[16];
    const float* Wf2 = (const float*)d_in[17];
    const float* bf2 = (const float*)d_in[18];
    const float* gf2 = (const float*)d_in[19];
    const float* bef2= (const float*)d_in[20];
    const float* Wf3 = (const float*)d_in[21];
    const float* bf3 = (const float*)d_in[22];
    float* out = (float*)d_out;

    cudaFuncSetAttribute(k_fusion, cudaFuncAttributeMaxDynamicSharedMemorySize,
                         FUSION_SMEM);

    k_feat<<<NP/4, 128>>>(x, W1, b1, g1, be1, Ws1, bs1, Ws2, bs2);
    k_knn_part<<<BB*16*4, 128>>>(x);
    k_knn_merge<<<NP/256, 256>>>();
    k_fcfn<<<NP/32, 256>>>(W2);
    k_edge<<<(NP*16)/256, 256>>>(b2, g2, be2);
    k_fusion<<<NP/TP, 256, FUSION_SMEM>>>(x, Wf1, bf1, gf1, bef1,
                                          Wf2, bf2, gf2, bef2, Wf3, bf3, out);
}

// round 7
// speedup vs baseline: 1.6597x; 1.2959x over previous
#include <cuda_runtime.h>
#include <math.h>

#define BB 8
#define NN 2048
#define NP (BB*NN)      // 16384 points
#define DD 64
#define KK 8
#define LL 3
#define H1 256
#define H2 128

// ---- scratch (device globals; no allocation allowed) ----
__device__ float g_feat[NP*DD];       // 4 MB
__device__ float g_fw[NP*LL];         // 192 KB
__device__ int   g_idx[NP*KK];        // 512 KB
__device__ float g_fcfn[NP*2*DD];     // 8 MB
__device__ float g_agg[NP*DD];        // 4 MB
__device__ float g_pd[NP*4*KK];       // 2 MB
__device__ int   g_pi[NP*4*KK];       // 2 MB

__device__ __forceinline__ float leaky_f(float v) { return v > 0.f ? v : 0.2f*v; }

// ---- packed f32x2 helpers ----
__device__ __forceinline__ unsigned long long fma2(unsigned long long a,
                                                   unsigned long long b,
                                                   unsigned long long c) {
    unsigned long long d;
    asm("fma.rn.f32x2 %0, %1, %2, %3;" : "=l"(d) : "l"(a), "l"(b), "l"(c));
    return d;
}
__device__ __forceinline__ unsigned long long pack2(float lo, float hi) {
    unsigned long long r;
    asm("mov.b64 %0, {%1, %2};" : "=l"(r) : "f"(lo), "f"(hi));
    return r;
}
__device__ __forceinline__ float2 unpack2(unsigned long long v) {
    float lo, hi;
    asm("mov.b64 {%0, %1}, %2;" : "=f"(lo), "=f"(hi) : "l"(v));
    return make_float2(lo, hi);
}

// ---- tf32 helpers ----
__device__ __forceinline__ unsigned int f2t(float f) {
    unsigned int u;
    asm("cvt.rna.tf32.f32 %0, %1;" : "=r"(u) : "f"(f));
    return u;
}
__device__ __forceinline__ void mma8(float* c,
    unsigned a0, unsigned a1, unsigned a2, unsigned a3,
    unsigned b0, unsigned b1)
{
    asm("mma.sync.aligned.m16n8k8.row.col.f32.tf32.tf32.f32 "
        "{%0,%1,%2,%3}, {%4,%5,%6,%7}, {%8,%9}, {%0,%1,%2,%3};"
        : "+f"(c[0]), "+f"(c[1]), "+f"(c[2]), "+f"(c[3])
        : "r"(a0), "r"(a1), "r"(a2), "r"(a3), "r"(b0), "r"(b1));
}

// ============================================================
// Kernel 1: warp-per-point feat + suppressor (unchanged)
// ============================================================
__global__ __launch_bounds__(128)
void k_feat(const float* __restrict__ x,
            const float* __restrict__ W1, const float* __restrict__ b1,
            const float* __restrict__ g1, const float* __restrict__ be1,
            const float* __restrict__ Ws1, const float* __restrict__ bs1,
            const float* __restrict__ Ws2, const float* __restrict__ bs2)
{
    int lane = threadIdx.x & 31;
    int p = blockIdx.x * 4 + (threadIdx.x >> 5);
    float x0 = x[p*3+0], x1 = x[p*3+1], x2 = x[p*3+2];

    float a0 = 0.f, a1 = 0.f, a2 = 0.f;
    #pragma unroll
    for (int h = 0; h < 2; ++h) {
        int d = lane + 32*h;
        float v = fmaf(x2, W1[128+d], fmaf(x1, W1[64+d], fmaf(x0, W1[d], b1[d])));
        v = v * g1[d] + be1[d];
        g_feat[(size_t)p*DD + d] = leaky_f(v);

        float hv = fmaf(x2, Ws1[128+d], fmaf(x1, Ws1[64+d], fmaf(x0, Ws1[d], bs1[d])));
        hv = hv > 0.f ? hv : 0.f;
        a0 = fmaf(hv, Ws2[d*3+0], a0);
        a1 = fmaf(hv, Ws2[d*3+1], a1);
        a2 = fmaf(hv, Ws2[d*3+2], a2);
    }
    #pragma unroll
    for (int off = 16; off > 0; off >>= 1) {
        a0 += __shfl_xor_sync(0xFFFFFFFF, a0, off);
        a1 += __shfl_xor_sync(0xFFFFFFFF, a1, off);
        a2 += __shfl_xor_sync(0xFFFFFFFF, a2, off);
    }
    if (lane == 0) {
        g_fw[p*3+0] = 1.f/(1.f + expf(-a0));
        g_fw[p*3+1] = 1.f/(1.f + expf(-a1));
        g_fw[p*3+2] = 1.f/(1.f + expf(-a2));
    }
}

// ============================================================
// Kernel 2a: KNN partial — 4 slices of 512 (unchanged)
// ============================================================
__global__ __launch_bounds__(128)
void k_knn_part(const float* __restrict__ x)
{
    __shared__ float4 xs[512];
    int tid = threadIdx.x;
    int s   = blockIdx.x & 3;
    int t   = (blockIdx.x >> 2) & 15;
    int b   = blockIdx.x >> 6;
    const float* xb = x + (size_t)b * NN * 3;
    int m0 = s * 512;

    for (int i = tid; i < 512; i += 128) {
        int m = m0 + i;
        float a0 = xb[m*3+0], a1 = xb[m*3+1], a2 = xb[m*3+2];
        xs[i] = make_float4(a0, a1, a2, a0*a0 + a1*a1 + a2*a2);
    }
    __syncthreads();

    int n = t*128 + tid;
    float c0 = xb[n*3+0], c1 = xb[n*3+1], c2 = xb[n*3+2];
    float cw = c0*c0 + c1*c1 + c2*c2;

    float bd[KK]; int bi[KK];
    #pragma unroll
    for (int k = 0; k < KK; ++k) { bd[k] = 3.4e38f; bi[k] = 0; }

    #pragma unroll 4
    for (int i = 0; i < 512; ++i) {
        float4 q = xs[i];
        float d2 = cw + q.w - 2.f*(c0*q.x + c1*q.y + c2*q.z);
        if (d2 < bd[KK-1]) {
            float v = d2; int vi = m0 + i;
            #pragma unroll
            for (int k = 0; k < KK; ++k) {
                if (v < bd[k]) {
                    float td = bd[k]; int ti = bi[k];
                    bd[k] = v; bi[k] = vi; v = td; vi = ti;
                }
            }
        }
    }
    int p = b*NN + n;
    #pragma unroll
    for (int k = 0; k < KK; ++k) {
        g_pd[(size_t)(s*KK + k)*NP + p] = bd[k];
        g_pi[(size_t)(s*KK + k)*NP + p] = bi[k];
    }
}

// ============================================================
// Kernel 2b: KNN merge (unchanged)
// ============================================================
__global__ __launch_bounds__(256)
void k_knn_merge()
{
    int p = blockIdx.x * 256 + threadIdx.x;
    float bd[KK]; int bi[KK];
    #pragma unroll
    for (int k = 0; k < KK; ++k) { bd[k] = 3.4e38f; bi[k] = 0; }

    #pragma unroll
    for (int s = 0; s < 4; ++s) {
        #pragma unroll
        for (int k2 = 0; k2 < KK; ++k2) {
            float v  = g_pd[(size_t)(s*KK + k2)*NP + p];
            int   vi = g_pi[(size_t)(s*KK + k2)*NP + p];
            if (v < bd[KK-1]) {
                #pragma unroll
                for (int k = 0; k < KK; ++k) {
                    if (v < bd[k]) {
                        float td = bd[k]; int ti = bi[k];
                        bd[k] = v; bi[k] = vi; v = td; vi = ti;
                    }
                }
            }
        }
    }
    #pragma unroll
    for (int k = 0; k < KK; ++k) g_idx[(size_t)p*KK + k] = bi[k];
}

// ============================================================
// Kernel 3 v3: [fc|fn] = feat @ W2cat. 16 pts/block, 128 thr,
// grid 1024 (fix grid-limited occupancy). FFMA2 micro-tile 4p x 4c.
// ============================================================
__global__ __launch_bounds__(128)
void k_fcfn(const float* __restrict__ W2)
{
    __shared__ __align__(16) float fs[64*20];   // [c*20 + p], 16 points
    __shared__ __align__(16) float ws[64*128];  // [c*128 + j]
    int tid = threadIdx.x;
    int pb  = blockIdx.x * 16;

    for (int i = tid; i < 16*64; i += 128) {
        int p = i >> 6, c = i & 63;
        fs[c*20 + p] = g_feat[(size_t)(pb+p)*DD + c];
    }
    // ws staged via float4: dst float4 index i: c=i>>5, j=(i&31)*4
    for (int i = tid; i < 2048; i += 128) {
        int c = i >> 5, jf = i & 31;
        float4 v = (jf < 16)
            ? *(const float4*)&W2[c*64 + jf*4]
            : *(const float4*)&W2[(64+c)*64 + (jf-16)*4];
        *(float4*)&ws[c*128 + jf*4] = v;
    }
    __syncthreads();

    int tp = tid >> 5, tc = tid & 31;
    int p0 = tp * 4, j0 = tc * 4;

    unsigned long long acc[8];
    unsigned long long z = pack2(0.f, 0.f);
    #pragma unroll
    for (int q = 0; q < 8; ++q) acc[q] = z;

    #pragma unroll 8
    for (int c = 0; c < 64; ++c) {
        float4 a = *(const float4*)&fs[c*20 + p0];           // broadcast
        ulonglong2 b = *(const ulonglong2*)&ws[c*128 + j0];
        unsigned long long a0 = pack2(a.x, a.x);
        unsigned long long a1 = pack2(a.y, a.y);
        unsigned long long a2 = pack2(a.z, a.z);
        unsigned long long a3 = pack2(a.w, a.w);
        acc[0] = fma2(a0, b.x, acc[0]); acc[1] = fma2(a0, b.y, acc[1]);
        acc[2] = fma2(a1, b.x, acc[2]); acc[3] = fma2(a1, b.y, acc[3]);
        acc[4] = fma2(a2, b.x, acc[4]); acc[5] = fma2(a2, b.y, acc[5]);
        acc[6] = fma2(a3, b.x, acc[6]); acc[7] = fma2(a3, b.y, acc[7]);
    }
    #pragma unroll
    for (int pp = 0; pp < 4; ++pp) {
        float2 v0 = unpack2(acc[pp*2+0]);
        float2 v1 = unpack2(acc[pp*2+1]);
        *(float4*)&g_fcfn[(size_t)(pb + p0 + pp)*128 + j0] =
            make_float4(v0.x, v0.y, v1.x, v1.y);
    }
}

// ============================================================
// Kernel 4: edge conv + max-agg (unchanged)
// ============================================================
__global__ __launch_bounds__(256)
void k_edge(const float* __restrict__ b2,
            const float* __restrict__ g2,
            const float* __restrict__ be2)
{
    int g = blockIdx.x * 256 + threadIdx.x;
    int p = g >> 4, d4 = (g & 15) * 4;
    int b = p >> 11;

    float4 fc = *(const float4*)&g_fcfn[(size_t)p*128 + d4];
    float4 Bv = *(const float4*)&b2[d4];
    float4 Gv = *(const float4*)&g2[d4];
    float4 Ev = *(const float4*)&be2[d4];
    float bx = fc.x + Bv.x, by = fc.y + Bv.y, bz = fc.z + Bv.z, bw = fc.w + Bv.w;

    int m[KK];
    const int* ip = g_idx + (size_t)p*KK;
    #pragma unroll
    for (int k = 0; k < KK; ++k) m[k] = ip[k];

    size_t rowb = (size_t)(b << 11) * 128 + 64 + d4;
    float mx0 = -3.4e38f, mx1 = -3.4e38f, mx2 = -3.4e38f, mx3 = -3.4e38f;
    #pragma unroll
    for (int k = 0; k < KK; ++k) {
        float4 fn = *(const float4*)&g_fcfn[rowb + (size_t)m[k]*128];
        mx0 = fmaxf(mx0, leaky_f((bx + fn.x) * Gv.x + Ev.x));
        mx1 = fmaxf(mx1, leaky_f((by + fn.y) * Gv.y + Ev.y));
        mx2 = fmaxf(mx2, leaky_f((bz + fn.z) * Gv.z + Ev.z));
        mx3 = fmaxf(mx3, leaky_f((bw + fn.w) * Gv.w + Ev.w));
    }
    *(float4*)&g_agg[(size_t)p*DD + d4] = make_float4(mx0, mx1, mx2, mx3);
}

// ============================================================
// Kernel 5 v3: fusion MLP via tf32 mma.sync (m16n8k8).
// 32 pts/block, 256 thr = 8 warps. Warp (mi,nj): mi=wid>>2 m16-tile,
// nj=wid&3 n-slice (64 cols L1 / 32 cols L2).
// smem: ws chunk [8704] | multi [32x204] (h2 [32x132] overlay) | h1 [32x260]
// ============================================================
#define MPAD  204
#define H1PAD 260
#define H2PAD 132
#define WS1   264
#define WS2   136
#define WSF   8704
#define MOFF  WSF
#define H1OFF (WSF + 32*MPAD)
#define FUS_SMEM ((WSF + 32*MPAD + 32*H1PAD) * 4)   // 94208 B

__global__ __launch_bounds__(256)
void k_fusion(const float* __restrict__ x,
              const float* __restrict__ Wf1, const float* __restrict__ bf1,
              const float* __restrict__ gf1, const float* __restrict__ bef1,
              const float* __restrict__ Wf2, const float* __restrict__ bf2,
              const float* __restrict__ gf2, const float* __restrict__ bef2,
              const float* __restrict__ Wf3, const float* __restrict__ bf3,
              float* __restrict__ out)
{
    extern __shared__ __align__(16) float smem[];
    float* ws    = smem;
    float* multi = smem + MOFF;
    float* h2_s  = multi;             // overlay (multi dead after layer 1)
    float* h1_s  = smem + H1OFF;

    int tid  = threadIdx.x;
    int pb   = blockIdx.x * 32;
    int wid  = tid >> 5, lane = tid & 31;
    int g    = lane >> 2, t = lane & 3;
    int m0   = (wid >> 2) * 16;
    int nj   = wid & 3;

    // Phase A: multi[p][kk] = agg[p][kk&63]*fw[p][kk>>6], tf32-rounded
    for (int i = tid; i < 32*192; i += 256) {
        int p = i / 192, kk = i - p*192;
        float v = g_agg[(size_t)(pb+p)*DD + (kk & 63)]
                * g_fw[(size_t)(pb+p)*3 + (kk >> 6)];
        multi[p*MPAD + kk] = __uint_as_float(f2t(v));
    }

    // ---- Layer 1: h1 = leaky(BN(multi @ Wf1)), M32 N256 K192 ----
    {
        float c1r[8][4];
        #pragma unroll
        for (int q = 0; q < 8; ++q)
            #pragma unroll
            for (int r = 0; r < 4; ++r) c1r[q][r] = 0.f;

        for (int kc = 0; kc < 192; kc += 32) {
            __syncthreads();
            for (int i = tid; i < 2048; i += 256) {
                int r = i >> 6, c4 = (i & 63) * 4;
                float4 wv = *(const float4*)&Wf1[(kc+r)*256 + c4];
                ws[r*WS1 + c4+0] = __uint_as_float(f2t(wv.x));
                ws[r*WS1 + c4+1] = __uint_as_float(f2t(wv.y));
                ws[r*WS1 + c4+2] = __uint_as_float(f2t(wv.z));
                ws[r*WS1 + c4+3] = __uint_as_float(f2t(wv.w));
            }
            __syncthreads();

            #pragma unroll
            for (int r8 = 0; r8 < 4; ++r8) {
                int k0 = r8 * 8;
                int cA = kc + k0 + t;
                unsigned a0 = __float_as_uint(multi[(m0+g)*MPAD + cA]);
                unsigned a1 = __float_as_uint(multi[(m0+g+8)*MPAD + cA]);
                unsigned a2 = __float_as_uint(multi[(m0+g)*MPAD + cA+4]);
                unsigned a3 = __float_as_uint(multi[(m0+g+8)*MPAD + cA+4]);
                #pragma unroll
                for (int nt = 0; nt < 8; ++nt) {
                    int n = nj*64 + nt*8 + g;
                    unsigned b0 = __float_as_uint(ws[(k0+t)*WS1 + n]);
                    unsigned b1 = __float_as_uint(ws[(k0+t+4)*WS1 + n]);
                    mma8(c1r[nt], a0, a1, a2, a3, b0, b1);
                }
            }
        }

        #pragma unroll
        for (int nt = 0; nt < 8; ++nt) {
            int j = nj*64 + nt*8 + 2*t;
            float b_0 = bf1[j],   g_0 = gf1[j],   e_0 = bef1[j];
            float b_1 = bf1[j+1], g_1 = gf1[j+1], e_1 = bef1[j+1];
            h1_s[(m0+g)*H1PAD + j]     = __uint_as_float(f2t(leaky_f((c1r[nt][0]+b_0)*g_0+e_0)));
            h1_s[(m0+g)*H1PAD + j+1]   = __uint_as_float(f2t(leaky_f((c1r[nt][1]+b_1)*g_1+e_1)));
            h1_s[(m0+g+8)*H1PAD + j]   = __uint_as_float(f2t(leaky_f((c1r[nt][2]+b_0)*g_0+e_0)));
            h1_s[(m0+g+8)*H1PAD + j+1] = __uint_as_float(f2t(leaky_f((c1r[nt][3]+b_1)*g_1+e_1)));
        }
    }

    // ---- Layer 2: h2 = leaky(BN(h1 @ Wf2)), M32 N128 K256 ----
    {
        float c2r[4][4];
        #pragma unroll
        for (int q = 0; q < 4; ++q)
            #pragma unroll
            for (int r = 0; r < 4; ++r) c2r[q][r] = 0.f;

        for (int kc = 0; kc < 256; kc += 64) {
            __syncthreads();
            for (int i = tid; i < 2048; i += 256) {
                int r = i >> 5, c4 = (i & 31) * 4;
                float4 wv = *(const float4*)&Wf2[(kc+r)*128 + c4];
                ws[r*WS2 + c4+0] = __uint_as_float(f2t(wv.x));
                ws[r*WS2 + c4+1] = __uint_as_float(f2t(wv.y));
                ws[r*WS2 + c4+2] = __uint_as_float(f2t(wv.z));
                ws[r*WS2 + c4+3] = __uint_as_float(f2t(wv.w));
            }
            __syncthreads();

            #pragma unroll
            for (int r8 = 0; r8 < 8; ++r8) {
                int k0 = r8 * 8;
                int cA = kc + k0 + t;
                unsigned a0 = __float_as_uint(h1_s[(m0+g)*H1PAD + cA]);
                unsigned a1 = __float_as_uint(h1_s[(m0+g+8)*H1PAD + cA]);
                unsigned a2 = __float_as_uint(h1_s[(m0+g)*H1PAD + cA+4]);
                unsigned a3 = __float_as_uint(h1_s[(m0+g+8)*H1PAD + cA+4]);
                #pragma unroll
                for (int nt = 0; nt < 4; ++nt) {
                    int n = nj*32 + nt*8 + g;
                    unsigned b0 = __float_as_uint(ws[(k0+t)*WS2 + n]);
                    unsigned b1 = __float_as_uint(ws[(k0+t+4)*WS2 + n]);
                    mma8(c2r[nt], a0, a1, a2, a3, b0, b1);
                }
            }
        }

        #pragma unroll
        for (int nt = 0; nt < 4; ++nt) {
            int j = nj*32 + nt*8 + 2*t;
            float b_0 = bf2[j],   g_0 = gf2[j],   e_0 = bef2[j];
            float b_1 = bf2[j+1], g_1 = gf2[j+1], e_1 = bef2[j+1];
            h2_s[(m0+g)*H2PAD + j]     = leaky_f((c2r[nt][0]+b_0)*g_0+e_0);
            h2_s[(m0+g)*H2PAD + j+1]   = leaky_f((c2r[nt][1]+b_1)*g_1+e_1);
            h2_s[(m0+g+8)*H2PAD + j]   = leaky_f((c2r[nt][2]+b_0)*g_0+e_0);
            h2_s[(m0+g+8)*H2PAD + j+1] = leaky_f((c2r[nt][3]+b_1)*g_1+e_1);
        }
    }
    __syncthreads();

    // ---- Layer 3 + residual (96 outputs, fp32) ----
    if (tid < 32*3) {
        int p = tid / 3, c = tid - p*3;
        float acc = 0.f;
        #pragma unroll 4
        for (int kk = 0; kk < 128; ++kk)
            acc = fmaf(h2_s[p*H2PAD + kk], Wf3[kk*3 + c], acc);
        size_t o = (size_t)(pb+p)*3 + c;
        out[o] = x[o] + 0.1f * (acc + bf3[c]);
    }
}

// ============================================================
extern "C" void kernel_launch(void* const* d_in, const int* in_sizes, int n_in,
                              void* d_out, int out_size)
{
    const float* x   = (const float*)d_in[0];
    const float* W1  = (const float*)d_in[1];
    const float* b1  = (const float*)d_in[2];
    const float* g1  = (const float*)d_in[3];
    const float* be1 = (const float*)d_in[4];
    const float* W2  = (const float*)d_in[5];
    const float* b2  = (const float*)d_in[6];
    const float* g2  = (const float*)d_in[7];
    const float* be2 = (const float*)d_in[8];
    const float* Ws1 = (const float*)d_in[9];
    const float* bs1 = (const float*)d_in[10];
    const float* Ws2 = (const float*)d_in[11];
    const float* bs2 = (const float*)d_in[12];
    const float* Wf1 = (const float*)d_in[13];
    const float* bf1 = (const float*)d_in[14];
    const float* gf1 = (const float*)d_in[15];
    const float* bef1= (const float*)d_in[16];
    const float* Wf2 = (const float*)d_in[17];
    const float* bf2 = (const float*)d_in[18];
    const float* gf2 = (const float*)d_in[19];
    const float* bef2= (const float*)d_in[20];
    const float* Wf3 = (const float*)d_in[21];
    const float* bf3 = (const float*)d_in[22];
    float* out = (float*)d_out;

    cudaFuncSetAttribute(k_fusion, cudaFuncAttributeMaxDynamicSharedMemorySize,
                         FUS_SMEM);

    k_feat<<<NP/4, 128>>>(x, W1, b1, g1, be1, Ws1, bs1, Ws2, bs2);
    k_knn_part<<<BB*16*4, 128>>>(x);
    k_knn_merge<<<NP/256, 256>>>();
    k_fcfn<<<NP/16, 128>>>(W2);
    k_edge<<<(NP*16)/256, 256>>>(b2, g2, be2);
    k_fusion<<<NP/32, 256, FUS_SMEM>>>(x, Wf1, bf1, gf1, bef1,
                                       Wf2, bf2, gf2, bef2, Wf3, bf3, out);
}

// round 9
// speedup vs baseline: 1.7627x; 1.0621x over previous
#include <cuda_runtime.h>
#include <math.h>

#define BB 8
#define NN 2048
#define NP (BB*NN)      // 16384 points
#define DD 64
#define KK 8
#define LL 3
#define H1 256
#define H2 128

// ---- scratch (device globals; no allocation allowed) ----
__device__ float g_feat[NP*DD];       // 4 MB
__device__ float g_fw[NP*LL];         // 192 KB
__device__ int   g_idx[NP*KK];        // 512 KB
__device__ float g_fcfn[NP*2*DD];     // 8 MB
__device__ float g_agg[NP*DD];        // 4 MB
__device__ float g_pd[NP*4*KK];       // 2 MB
__device__ int   g_pi[NP*4*KK];       // 2 MB

__device__ __forceinline__ float leaky_f(float v) { return v > 0.f ? v : 0.2f*v; }

// ---- tf32 helpers ----
__device__ __forceinline__ unsigned int f2t(float f) {
    unsigned int u;
    asm("cvt.rna.tf32.f32 %0, %1;" : "=r"(u) : "f"(f));
    return u;
}
__device__ __forceinline__ void mma8(float* c,
    unsigned a0, unsigned a1, unsigned a2, unsigned a3,
    unsigned b0, unsigned b1)
{
    asm("mma.sync.aligned.m16n8k8.row.col.f32.tf32.tf32.f32 "
        "{%0,%1,%2,%3}, {%4,%5,%6,%7}, {%8,%9}, {%0,%1,%2,%3};"
        : "+f"(c[0]), "+f"(c[1]), "+f"(c[2]), "+f"(c[3])
        : "r"(a0), "r"(a1), "r"(a2), "r"(a3), "r"(b0), "r"(b1));
}

// ============================================================
// Kernel 1: warp-per-point feat + suppressor (unchanged)
// ============================================================
__global__ __launch_bounds__(128)
void k_feat(const float* __restrict__ x,
            const float* __restrict__ W1, const float* __restrict__ b1,
            const float* __restrict__ g1, const float* __restrict__ be1,
            const float* __restrict__ Ws1, const float* __restrict__ bs1,
            const float* __restrict__ Ws2, const float* __restrict__ bs2)
{
    int lane = threadIdx.x & 31;
    int p = blockIdx.x * 4 + (threadIdx.x >> 5);
    float x0 = x[p*3+0], x1 = x[p*3+1], x2 = x[p*3+2];

    float a0 = 0.f, a1 = 0.f, a2 = 0.f;
    #pragma unroll
    for (int h = 0; h < 2; ++h) {
        int d = lane + 32*h;
        float v = fmaf(x2, W1[128+d], fmaf(x1, W1[64+d], fmaf(x0, W1[d], b1[d])));
        v = v * g1[d] + be1[d];
        g_feat[(size_t)p*DD + d] = leaky_f(v);

        float hv = fmaf(x2, Ws1[128+d], fmaf(x1, Ws1[64+d], fmaf(x0, Ws1[d], bs1[d])));
        hv = hv > 0.f ? hv : 0.f;
        a0 = fmaf(hv, Ws2[d*3+0], a0);
        a1 = fmaf(hv, Ws2[d*3+1], a1);
        a2 = fmaf(hv, Ws2[d*3+2], a2);
    }
    #pragma unroll
    for (int off = 16; off > 0; off >>= 1) {
        a0 += __shfl_xor_sync(0xFFFFFFFF, a0, off);
        a1 += __shfl_xor_sync(0xFFFFFFFF, a1, off);
        a2 += __shfl_xor_sync(0xFFFFFFFF, a2, off);
    }
    if (lane == 0) {
        g_fw[p*3+0] = 1.f/(1.f + expf(-a0));
        g_fw[p*3+1] = 1.f/(1.f + expf(-a1));
        g_fw[p*3+2] = 1.f/(1.f + expf(-a2));
    }
}

// ============================================================
// Kernel 2a: KNN partial — 4 slices of 512 (unchanged)
// ============================================================
__global__ __launch_bounds__(128)
void k_knn_part(const float* __restrict__ x)
{
    __shared__ float4 xs[512];
    int tid = threadIdx.x;
    int s   = blockIdx.x & 3;
    int t   = (blockIdx.x >> 2) & 15;
    int b   = blockIdx.x >> 6;
    const float* xb = x + (size_t)b * NN * 3;
    int m0 = s * 512;

    for (int i = tid; i < 512; i += 128) {
        int m = m0 + i;
        float a0 = xb[m*3+0], a1 = xb[m*3+1], a2 = xb[m*3+2];
        xs[i] = make_float4(a0, a1, a2, a0*a0 + a1*a1 + a2*a2);
    }
    __syncthreads();

    int n = t*128 + tid;
    float c0 = xb[n*3+0], c1 = xb[n*3+1], c2 = xb[n*3+2];
    float cw = c0*c0 + c1*c1 + c2*c2;

    float bd[KK]; int bi[KK];
    #pragma unroll
    for (int k = 0; k < KK; ++k) { bd[k] = 3.4e38f; bi[k] = 0; }

    #pragma unroll 4
    for (int i = 0; i < 512; ++i) {
        float4 q = xs[i];
        float d2 = cw + q.w - 2.f*(c0*q.x + c1*q.y + c2*q.z);
        if (d2 < bd[KK-1]) {
            float v = d2; int vi = m0 + i;
            #pragma unroll
            for (int k = 0; k < KK; ++k) {
                if (v < bd[k]) {
                    float td = bd[k]; int ti = bi[k];
                    bd[k] = v; bi[k] = vi; v = td; vi = ti;
                }
            }
        }
    }
    int p = b*NN + n;
    #pragma unroll
    for (int k = 0; k < KK; ++k) {
        g_pd[(size_t)(s*KK + k)*NP + p] = bd[k];
        g_pi[(size_t)(s*KK + k)*NP + p] = bi[k];
    }
}

// ============================================================
// Kernel 2b: KNN merge (unchanged)
// ============================================================
__global__ __launch_bounds__(256)
void k_knn_merge()
{
    int p = blockIdx.x * 256 + threadIdx.x;
    float bd[KK]; int bi[KK];
    #pragma unroll
    for (int k = 0; k < KK; ++k) { bd[k] = 3.4e38f; bi[k] = 0; }

    #pragma unroll
    for (int s = 0; s < 4; ++s) {
        #pragma unroll
        for (int k2 = 0; k2 < KK; ++k2) {
            float v  = g_pd[(size_t)(s*KK + k2)*NP + p];
            int   vi = g_pi[(size_t)(s*KK + k2)*NP + p];
            if (v < bd[KK-1]) {
                #pragma unroll
                for (int k = 0; k < KK; ++k) {
                    if (v < bd[k]) {
                        float td = bd[k]; int ti = bi[k];
                        bd[k] = v; bi[k] = vi; v = td; vi = ti;
                    }
                }
            }
        }
    }
    #pragma unroll
    for (int k = 0; k < KK; ++k) g_idx[(size_t)p*KK + k] = bi[k];
}

// ============================================================
// Kernel 3 v4: [fc|fn] = feat @ W2cat via tf32 mma.
// 64 pts/block, 256 thr = 8 warps, grid 256.
// Warp = (m16-tile wid>>1, n64-half wid&1). K=64 = 8 mma k-steps.
// fs stride 76 (≡12 mod 32), ws stride 136 (≡8 mod 32): conflict-free.
// ============================================================
#define FC_FP 76
#define FC_WP 136
__global__ __launch_bounds__(256)
void k_fcfn(const float* __restrict__ W2)
{
    __shared__ float fs[64*FC_FP];   // 19.5 KB
    __shared__ float ws[64*FC_WP];   // 34.8 KB
    int tid = threadIdx.x;
    int pb  = blockIdx.x * 64;

    // stage feat tile (tf32-rounded): 1024 float4
    for (int i = tid; i < 64*16; i += 256) {
        int p = i >> 4, c4 = (i & 15) * 4;
        float4 v = *(const float4*)&g_feat[(size_t)(pb+p)*DD + c4];
        fs[p*FC_FP + c4+0] = __uint_as_float(f2t(v.x));
        fs[p*FC_FP + c4+1] = __uint_as_float(f2t(v.y));
        fs[p*FC_FP + c4+2] = __uint_as_float(f2t(v.z));
        fs[p*FC_FP + c4+3] = __uint_as_float(f2t(v.w));
    }
    // stage W2cat [c][j] (tf32-rounded): 2048 float4
    for (int i = tid; i < 64*32; i += 256) {
        int c = i >> 5, jf = i & 31;
        float4 v = (jf < 16)
            ? *(const float4*)&W2[c*64 + jf*4]
            : *(const float4*)&W2[(64+c)*64 + (jf-16)*4];
        int j0 = jf * 4;
        ws[c*FC_WP + j0+0] = __uint_as_float(f2t(v.x));
        ws[c*FC_WP + j0+1] = __uint_as_float(f2t(v.y));
        ws[c*FC_WP + j0+2] = __uint_as_float(f2t(v.z));
        ws[c*FC_WP + j0+3] = __uint_as_float(f2t(v.w));
    }
    __syncthreads();

    int wid = tid >> 5, lane = tid & 31;
    int g = lane >> 2, t = lane & 3;
    int m0 = (wid >> 1) * 16;
    int nh = wid & 1;

    float acc[8][4];
    #pragma unroll
    for (int q = 0; q < 8; ++q)
        #pragma unroll
        for (int r = 0; r < 4; ++r) acc[q][r] = 0.f;

    #pragma unroll
    for (int r8 = 0; r8 < 8; ++r8) {
        int k0 = r8 * 8;
        unsigned a0 = __float_as_uint(fs[(m0+g)*FC_FP + k0+t]);
        unsigned a1 = __float_as_uint(fs[(m0+g+8)*FC_FP + k0+t]);
        unsigned a2 = __float_as_uint(fs[(m0+g)*FC_FP + k0+t+4]);
        unsigned a3 = __float_as_uint(fs[(m0+g+8)*FC_FP + k0+t+4]);
        #pragma unroll
        for (int nt = 0; nt < 8; ++nt) {
            int n = nh*64 + nt*8 + g;
            unsigned b0 = __float_as_uint(ws[(k0+t)*FC_WP + n]);
            unsigned b1 = __float_as_uint(ws[(k0+t+4)*FC_WP + n]);
            mma8(acc[nt], a0, a1, a2, a3, b0, b1);
        }
    }

    // epilogue: c[0],c[1] -> row m0+g, cols j,j+1 ; c[2],c[3] -> row m0+g+8
    #pragma unroll
    for (int nt = 0; nt < 8; ++nt) {
        int j = nh*64 + nt*8 + 2*t;
        *(float2*)&g_fcfn[(size_t)(pb+m0+g)*128 + j]   = make_float2(acc[nt][0], acc[nt][1]);
        *(float2*)&g_fcfn[(size_t)(pb+m0+g+8)*128 + j] = make_float2(acc[nt][2], acc[nt][3]);
    }
}

// ============================================================
// Kernel 4: edge conv + max-agg (unchanged)
// ============================================================
__global__ __launch_bounds__(256)
void k_edge(const float* __restrict__ b2,
            const float* __restrict__ g2,
            const float* __restrict__ be2)
{
    int g = blockIdx.x * 256 + threadIdx.x;
    int p = g >> 4, d4 = (g & 15) * 4;
    int b = p >> 11;

    float4 fc = *(const float4*)&g_fcfn[(size_t)p*128 + d4];
    float4 Bv = *(const float4*)&b2[d4];
    float4 Gv = *(const float4*)&g2[d4];
    float4 Ev = *(const float4*)&be2[d4];
    float bx = fc.x + Bv.x, by = fc.y + Bv.y, bz = fc.z + Bv.z, bw = fc.w + Bv.w;

    int m[KK];
    const int* ip = g_idx + (size_t)p*KK;
    #pragma unroll
    for (int k = 0; k < KK; ++k) m[k] = ip[k];

    size_t rowb = (size_t)(b << 11) * 128 + 64 + d4;
    float mx0 = -3.4e38f, mx1 = -3.4e38f, mx2 = -3.4e38f, mx3 = -3.4e38f;
    #pragma unroll
    for (int k = 0; k < KK; ++k) {
        float4 fn = *(const float4*)&g_fcfn[rowb + (size_t)m[k]*128];
        mx0 = fmaxf(mx0, leaky_f((bx + fn.x) * Gv.x + Ev.x));
        mx1 = fmaxf(mx1, leaky_f((by + fn.y) * Gv.y + Ev.y));
        mx2 = fmaxf(mx2, leaky_f((bz + fn.z) * Gv.z + Ev.z));
        mx3 = fmaxf(mx3, leaky_f((bw + fn.w) * Gv.w + Ev.w));
    }
    *(float4*)&g_agg[(size_t)p*DD + d4] = make_float4(mx0, mx1, mx2, mx3);
}

// ============================================================
// Kernel 5 v3: fusion MLP via tf32 mma.sync (unchanged from R7)
// ============================================================
#define MPAD  204
#define H1PAD 260
#define H2PAD 132
#define WS1   264
#define WS2   136
#define WSF   8704
#define MOFF  WSF
#define H1OFF (WSF + 32*MPAD)
#define FUS_SMEM ((WSF + 32*MPAD + 32*H1PAD) * 4)   // 94208 B

__global__ __launch_bounds__(256)
void k_fusion(const float* __restrict__ x,
              const float* __restrict__ Wf1, const float* __restrict__ bf1,
              const float* __restrict__ gf1, const float* __restrict__ bef1,
              const float* __restrict__ Wf2, const float* __restrict__ bf2,
              const float* __restrict__ gf2, const float* __restrict__ bef2,
              const float* __restrict__ Wf3, const float* __restrict__ bf3,
              float* __restrict__ out)
{
    extern __shared__ __align__(16) float smem[];
    float* ws    = smem;
    float* multi = smem + MOFF;
    float* h2_s  = multi;             // overlay (multi dead after layer 1)
    float* h1_s  = smem + H1OFF;

    int tid  = threadIdx.x;
    int pb   = blockIdx.x * 32;
    int wid  = tid >> 5, lane = tid & 31;
    int g    = lane >> 2, t = lane & 3;
    int m0   = (wid >> 2) * 16;
    int nj   = wid & 3;

    // Phase A: multi[p][kk] = agg[p][kk&63]*fw[p][kk>>6], tf32-rounded
    for (int i = tid; i < 32*192; i += 256) {
        int p = i / 192, kk = i - p*192;
        float v = g_agg[(size_t)(pb+p)*DD + (kk & 63)]
                * g_fw[(size_t)(pb+p)*3 + (kk >> 6)];
        multi[p*MPAD + kk] = __uint_as_float(f2t(v));
    }

    // ---- Layer 1: h1 = leaky(BN(multi @ Wf1)), M32 N256 K192 ----
    {
        float c1r[8][4];
        #pragma unroll
        for (int q = 0; q < 8; ++q)
            #pragma unroll
            for (int r = 0; r < 4; ++r) c1r[q][r] = 0.f;

        for (int kc = 0; kc < 192; kc += 32) {
            __syncthreads();
            for (int i = tid; i < 2048; i += 256) {
                int r = i >> 6, c4 = (i & 63) * 4;
                float4 wv = *(const float4*)&Wf1[(kc+r)*256 + c4];
                ws[r*WS1 + c4+0] = __uint_as_float(f2t(wv.x));
                ws[r*WS1 + c4+1] = __uint_as_float(f2t(wv.y));
                ws[r*WS1 + c4+2] = __uint_as_float(f2t(wv.z));
                ws[r*WS1 + c4+3] = __uint_as_float(f2t(wv.w));
            }
            __syncthreads();

            #pragma unroll
            for (int r8 = 0; r8 < 4; ++r8) {
                int k0 = r8 * 8;
                int cA = kc + k0 + t;
                unsigned a0 = __float_as_uint(multi[(m0+g)*MPAD + cA]);
                unsigned a1 = __float_as_uint(multi[(m0+g+8)*MPAD + cA]);
                unsigned a2 = __float_as_uint(multi[(m0+g)*MPAD + cA+4]);
                unsigned a3 = __float_as_uint(multi[(m0+g+8)*MPAD + cA+4]);
                #pragma unroll
                for (int nt = 0; nt < 8; ++nt) {
                    int n = nj*64 + nt*8 + g;
                    unsigned b0 = __float_as_uint(ws[(k0+t)*WS1 + n]);
                    unsigned b1 = __float_as_uint(ws[(k0+t+4)*WS1 + n]);
                    mma8(c1r[nt], a0, a1, a2, a3, b0, b1);
                }
            }
        }

        #pragma unroll
        for (int nt = 0; nt < 8; ++nt) {
            int j = nj*64 + nt*8 + 2*t;
            float b_0 = bf1[j],   g_0 = gf1[j],   e_0 = bef1[j];
            float b_1 = bf1[j+1], g_1 = gf1[j+1], e_1 = bef1[j+1];
            h1_s[(m0+g)*H1PAD + j]     = __uint_as_float(f2t(leaky_f((c1r[nt][0]+b_0)*g_0+e_0)));
            h1_s[(m0+g)*H1PAD + j+1]   = __uint_as_float(f2t(leaky_f((c1r[nt][1]+b_1)*g_1+e_1)));
            h1_s[(m0+g+8)*H1PAD + j]   = __uint_as_float(f2t(leaky_f((c1r[nt][2]+b_0)*g_0+e_0)));
            h1_s[(m0+g+8)*H1PAD + j+1] = __uint_as_float(f2t(leaky_f((c1r[nt][3]+b_1)*g_1+e_1)));
        }
    }

    // ---- Layer 2: h2 = leaky(BN(h1 @ Wf2)), M32 N128 K256 ----
    {
        float c2r[4][4];
        #pragma unroll
        for (int q = 0; q < 4; ++q)
            #pragma unroll
            for (int r = 0; r < 4; ++r) c2r[q][r] = 0.f;

        for (int kc = 0; kc < 256; kc += 64) {
            __syncthreads();
            for (int i = tid; i < 2048; i += 256) {
                int r = i >> 5, c4 = (i & 31) * 4;
                float4 wv = *(const float4*)&Wf2[(kc+r)*128 + c4];
                ws[r*WS2 + c4+0] = __uint_as_float(f2t(wv.x));
                ws[r*WS2 + c4+1] = __uint_as_float(f2t(wv.y));
                ws[r*WS2 + c4+2] = __uint_as_float(f2t(wv.z));
                ws[r*WS2 + c4+3] = __uint_as_float(f2t(wv.w));
            }
            __syncthreads();

            #pragma unroll
            for (int r8 = 0; r8 < 8; ++r8) {
                int k0 = r8 * 8;
                int cA = kc + k0 + t;
                unsigned a0 = __float_as_uint(h1_s[(m0+g)*H1PAD + cA]);
                unsigned a1 = __float_as_uint(h1_s[(m0+g+8)*H1PAD + cA]);
                unsigned a2 = __float_as_uint(h1_s[(m0+g)*H1PAD + cA+4]);
                unsigned a3 = __float_as_uint(h1_s[(m0+g+8)*H1PAD + cA+4]);
                #pragma unroll
                for (int nt = 0; nt < 4; ++nt) {
                    int n = nj*32 + nt*8 + g;
                    unsigned b0 = __float_as_uint(ws[(k0+t)*WS2 + n]);
                    unsigned b1 = __float_as_uint(ws[(k0+t+4)*WS2 + n]);
                    mma8(c2r[nt], a0, a1, a2, a3, b0, b1);
                }
            }
        }

        #pragma unroll
        for (int nt = 0; nt < 4; ++nt) {
            int j = nj*32 + nt*8 + 2*t;
            float b_0 = bf2[j],   g_0 = gf2[j],   e_0 = bef2[j];
            float b_1 = bf2[j+1], g_1 = gf2[j+1], e_1 = bef2[j+1];
            h2_s[(m0+g)*H2PAD + j]     = leaky_f((c2r[nt][0]+b_0)*g_0+e_0);
            h2_s[(m0+g)*H2PAD + j+1]   = leaky_f((c2r[nt][1]+b_1)*g_1+e_1);
            h2_s[(m0+g+8)*H2PAD + j]   = leaky_f((c2r[nt][2]+b_0)*g_0+e_0);
            h2_s[(m0+g+8)*H2PAD + j+1] = leaky_f((c2r[nt][3]+b_1)*g_1+e_1);
        }
    }
    __syncthreads();

    // ---- Layer 3 + residual (96 outputs, fp32) ----
    if (tid < 32*3) {
        int p = tid / 3, c = tid - p*3;
        float acc = 0.f;
        #pragma unroll 4
        for (int kk = 0; kk < 128; ++kk)
            acc = fmaf(h2_s[p*H2PAD + kk], Wf3[kk*3 + c], acc);
        size_t o = (size_t)(pb+p)*3 + c;
        out[o] = x[o] + 0.1f * (acc + bf3[c]);
    }
}

// ============================================================
extern "C" void kernel_launch(void* const* d_in, const int* in_sizes, int n_in,
                              void* d_out, int out_size)
{
    const float* x   = (const float*)d_in[0];
    const float* W1  = (const float*)d_in[1];
    const float* b1  = (const float*)d_in[2];
    const float* g1  = (const float*)d_in[3];
    const float* be1 = (const float*)d_in[4];
    const float* W2  = (const float*)d_in[5];
    const float* b2  = (const float*)d_in[6];
    const float* g2  = (const float*)d_in[7];
    const float* be2 = (const float*)d_in[8];
    const float* Ws1 = (const float*)d_in[9];
    const float* bs1 = (const float*)d_in[10];
    const float* Ws2 = (const float*)d_in[11];
    const float* bs2 = (const float*)d_in[12];
    const float* Wf1 = (const float*)d_in[13];
    const float* bf1 = (const float*)d_in[14];
    const float* gf1 = (const float*)d_in[15];
    const float* bef1= (const float*)d_in[16];
    const float* Wf2 = (const float*)d_in[17];
    const float* bf2 = (const float*)d_in[18];
    const float* gf2 = (const float*)d_in[19];
    const float* bef2= (const float*)d_in[20];
    const float* Wf3 = (const float*)d_in[21];
    const float* bf3 = (const float*)d_in[22];
    float* out = (float*)d_out;

    cudaFuncSetAttribute(k_fusion, cudaFuncAttributeMaxDynamicSharedMemorySize,
                         FUS_SMEM);

    k_feat<<<NP/4, 128>>>(x, W1, b1, g1, be1, Ws1, bs1, Ws2, bs2);
    k_knn_part<<<BB*16*4, 128>>>(x);
    k_knn_merge<<<NP/256, 256>>>();
    k_fcfn<<<NP/64, 256>>>(W2);
    k_edge<<<(NP*16)/256, 256>>>(b2, g2, be2);
    k_fusion<<<NP/32, 256, FUS_SMEM>>>(x, Wf1, bf1, gf1, bef1,
                                       Wf2, bf2, gf2, bef2, Wf3, bf3, out);
}